// round 11
// baseline (speedup 1.0000x reference)
#include <cuda_runtime.h>
#include <cuda_bf16.h>
#include <cstdint>

#define DATA_DIM 88
#define HID 16
#define ND 48
#define CD 176
#define TOK_TILE 128
#define THREADS 256

// strides in u32 (pair) units; all ≡ 28 (mod 32) => conflict-free fragment loads
#define SA1 92     // A1: 88 data pairs
#define SB1 92     // B1: 88 data pairs
#define SH  28     // H:  24 data pairs
#define SB2 28     // B2: 24 data pairs

// SMEM byte offsets
#define OFF_A1HI 0
#define OFF_A1LO 47104
#define OFF_B1HI 94208
#define OFF_B1LO 111872
#define OFF_HHI  129536
#define OFF_HLO  143872
#define OFF_B2HI 158208
#define OFF_B2LO 168064
#define OFF_WXH  177920
#define OFF_WWH  180992
#define OFF_BSUM 184064
#define OFF_BHL  184256
#define OFF_XI   184608
#define OFF_WI   185120
#define SMEM_TOTAL 185632

__device__ __forceinline__ uint32_t cvt_bf2(float lo, float hi) {
    uint32_t r;
    asm("cvt.rn.bf16x2.f32 %0, %1, %2;" : "=r"(r) : "f"(hi), "f"(lo));
    return r;
}
__device__ __forceinline__ float bfr(float v) {
    return __bfloat162float(__float2bfloat16_rn(v));
}
__device__ __forceinline__ void mma_bf16(float* c,
                                         uint32_t a0, uint32_t a1, uint32_t a2, uint32_t a3,
                                         uint32_t b0, uint32_t b1) {
    asm volatile(
        "mma.sync.aligned.m16n8k16.row.col.f32.bf16.bf16.f32 "
        "{%0,%1,%2,%3}, {%4,%5,%6,%7}, {%8,%9}, {%0,%1,%2,%3};\n"
        : "+f"(c[0]), "+f"(c[1]), "+f"(c[2]), "+f"(c[3])
        : "r"(a0), "r"(a1), "r"(a2), "r"(a3), "r"(b0), "r"(b1));
}

// conv output for tone d (d is a compile-time constant after unroll)
#define CONV(d) fmaxf(fmaf(wc2, ((d) == 87 ? 0.f : yr[(d) + 1]), \
                      fmaf(wc1, yr[d], fmaf(wc0, ((d) == 0 ? 0.f : yr[(d) - 1]), bc))), 0.f)

__global__ void __launch_bounds__(THREADS, 1)
model8_mma(const int* __restrict__ gw, const int* __restrict__ gx,
           const float* __restrict__ gy,
           const float* __restrict__ Wxh, const float* __restrict__ bxh,
           const float* __restrict__ Wwh, const float* __restrict__ bwh,
           const float* __restrict__ Wyh, const float* __restrict__ byh,
           const float* __restrict__ Wconv, const float* __restrict__ bconv,
           const float* __restrict__ Whl, const float* __restrict__ bhl,
           float* __restrict__ out)
{
    extern __shared__ char smem[];
    uint32_t* A1hi = (uint32_t*)(smem + OFF_A1HI);
    uint32_t* A1lo = (uint32_t*)(smem + OFF_A1LO);
    uint32_t* Hhi  = (uint32_t*)(smem + OFF_HHI);
    uint32_t* Hlo  = (uint32_t*)(smem + OFF_HLO);
    float*    sWxh = (float*)(smem + OFF_WXH);
    float*    sWwh = (float*)(smem + OFF_WWH);
    float*    sBsum= (float*)(smem + OFF_BSUM);
    float*    sBhl = (float*)(smem + OFF_BHL);
    int*      sXI  = (int*)(smem + OFF_XI);
    int*      sWI  = (int*)(smem + OFF_WI);

    const int tid  = threadIdx.x;
    const int tile = blockIdx.x;

    // ---- per-thread conv assignment: token = tid/2, channel = tid&1 ----
    const int token = tid >> 1;
    const int ch    = tid & 1;

    // load y row into registers (22 x LDG.128)
    float yr[DATA_DIM];
    {
        const float4* yrow = (const float4*)(gy + ((size_t)tile * TOK_TILE + token) * DATA_DIM);
        #pragma unroll
        for (int q = 0; q < 22; q++) {
            float4 v = yrow[q];
            yr[4*q] = v.x; yr[4*q+1] = v.y; yr[4*q+2] = v.z; yr[4*q+3] = v.w;
        }
    }
    const float wc0 = __ldg(&Wconv[ch * 3 + 0]);
    const float wc1 = __ldg(&Wconv[ch * 3 + 1]);
    const float wc2 = __ldg(&Wconv[ch * 3 + 2]);
    const float bc  = __ldg(&bconv[ch]);

    // ---- stage weights (bf16 hi/lo split), gathers, biases, indices ----
    for (int i = tid; i < ND * CD; i += THREADS) {
        int n = i / CD, k = i % CD;
        float v = Wyh[i];
        float h = bfr(v);
        uint32_t bo = (uint32_t)(n * SA1 + (k >> 1)) * 4u + (uint32_t)(k & 1) * 2u;
        *(__nv_bfloat16*)(smem + OFF_B1HI + bo) = __float2bfloat16_rn(v);
        *(__nv_bfloat16*)(smem + OFF_B1LO + bo) = __float2bfloat16_rn(v - h);
    }
    for (int i = tid; i < DATA_DIM * ND; i += THREADS) {
        int d = i / ND, k = i % ND;
        float v = Whl[i];
        float h = bfr(v);
        uint32_t bo = (uint32_t)(d * SB2 + (k >> 1)) * 4u + (uint32_t)(k & 1) * 2u;
        *(__nv_bfloat16*)(smem + OFF_B2HI + bo) = __float2bfloat16_rn(v);
        *(__nv_bfloat16*)(smem + OFF_B2LO + bo) = __float2bfloat16_rn(v - h);
    }
    for (int i = tid; i < ND * HID; i += THREADS) {
        int n = i / HID, h = i % HID;
        sWxh[h * ND + n] = Wxh[i];
        sWwh[h * ND + n] = Wwh[i];
    }
    for (int i = tid; i < ND; i += THREADS) sBsum[i] = bxh[i] + bwh[i] + byh[i];
    for (int i = tid; i < DATA_DIM; i += THREADS) sBhl[i] = bhl[i];
    for (int i = tid; i < TOK_TILE; i += THREADS) {
        sXI[i] = gx[(size_t)tile * TOK_TILE + i];
        sWI[i] = gw[(size_t)tile * TOK_TILE + i];
    }
    __syncthreads();   // the only block barrier

    // ---- conv + bf16 split -> A1 (each warp writes exactly its own 16 tokens) ----
    {
        uint32_t base = (uint32_t)token * SA1 + (uint32_t)ch * 44u;  // u32 index, 16B-aligned
        uint4* dh = (uint4*)(A1hi + base);
        uint4* dl = (uint4*)(A1lo + base);
        #pragma unroll
        for (int q = 0; q < 11; q++) {
            float c0 = CONV(8*q+0), c1 = CONV(8*q+1), c2 = CONV(8*q+2), c3 = CONV(8*q+3);
            float c4 = CONV(8*q+4), c5 = CONV(8*q+5), c6 = CONV(8*q+6), c7 = CONV(8*q+7);
            uint4 H4, L4;
            H4.x = cvt_bf2(c0, c1); H4.y = cvt_bf2(c2, c3);
            H4.z = cvt_bf2(c4, c5); H4.w = cvt_bf2(c6, c7);
            L4.x = cvt_bf2(c0 - bfr(c0), c1 - bfr(c1));
            L4.y = cvt_bf2(c2 - bfr(c2), c3 - bfr(c3));
            L4.z = cvt_bf2(c4 - bfr(c4), c5 - bfr(c5));
            L4.w = cvt_bf2(c6 - bfr(c6), c7 - bfr(c7));
            dh[q] = H4;
            dl[q] = L4;
        }
    }
    __syncwarp();

    const int w    = tid >> 5;
    const int lane = tid & 31;
    const int g    = lane >> 2;
    const int tg   = lane & 3;

    // ---- GEMM1: [128x176] x [176x48]^T, split-bf16 3 passes ----
    float acc[6][4];
    #pragma unroll
    for (int j = 0; j < 6; j++)
        acc[j][0] = acc[j][1] = acc[j][2] = acc[j][3] = 0.f;

    const int arow1 = (16 * w + g) * SA1;
    #pragma unroll 1
    for (int pass = 0; pass < 3; pass++) {
        const uint32_t* Ab = (pass == 2) ? A1lo : A1hi;
        const uint32_t* Bb = (pass == 1) ? (const uint32_t*)(smem + OFF_B1LO)
                                         : (const uint32_t*)(smem + OFF_B1HI);
        #pragma unroll
        for (int ks = 0; ks < 11; ks++) {
            int ai = arow1 + tg + 8 * ks;
            uint32_t a0 = Ab[ai],            a1 = Ab[ai + 8 * SA1];
            uint32_t a2 = Ab[ai + 4],        a3 = Ab[ai + 8 * SA1 + 4];
            #pragma unroll
            for (int j = 0; j < 6; j++) {
                int bi = (8 * j + g) * SB1 + tg + 8 * ks;
                mma_bf16(acc[j], a0, a1, a2, a3, Bb[bi], Bb[bi + 4]);
            }
        }
    }

    // ---- epilogue 1: + gathers + bias, relu, split -> H (intra-warp) ----
    {
        const int tok0 = 16 * w + g, tok1 = tok0 + 8;
        const int xi0 = sXI[tok0], wi0 = sWI[tok0];
        const int xi1 = sXI[tok1], wi1 = sWI[tok1];
        #pragma unroll
        for (int j = 0; j < 6; j++) {
            int n0 = 8 * j + 2 * tg;
            float bs0 = sBsum[n0],               bs1 = sBsum[n0 + 1];
            float h0 = fmaxf(acc[j][0] + bs0 + sWxh[xi0 * ND + n0]     + sWwh[wi0 * ND + n0],     0.f);
            float h1 = fmaxf(acc[j][1] + bs1 + sWxh[xi0 * ND + n0 + 1] + sWwh[wi0 * ND + n0 + 1], 0.f);
            float h2 = fmaxf(acc[j][2] + bs0 + sWxh[xi1 * ND + n0]     + sWwh[wi1 * ND + n0],     0.f);
            float h3 = fmaxf(acc[j][3] + bs1 + sWxh[xi1 * ND + n0 + 1] + sWwh[wi1 * ND + n0 + 1], 0.f);
            int i0 = tok0 * SH + 4 * j + tg;
            int i1 = tok1 * SH + 4 * j + tg;
            Hhi[i0] = cvt_bf2(h0, h1);
            Hlo[i0] = cvt_bf2(h0 - bfr(h0), h1 - bfr(h1));
            Hhi[i1] = cvt_bf2(h2, h3);
            Hlo[i1] = cvt_bf2(h2 - bfr(h2), h3 - bfr(h3));
        }
    }
    __syncwarp();

    // ---- GEMM2: [128x48] x [48x88]^T, split-bf16 3 passes ----
    float acc2[11][4];
    #pragma unroll
    for (int j = 0; j < 11; j++)
        acc2[j][0] = acc2[j][1] = acc2[j][2] = acc2[j][3] = 0.f;

    const int arow2 = (16 * w + g) * SH;
    #pragma unroll 1
    for (int pass = 0; pass < 3; pass++) {
        const uint32_t* Ab = (pass == 2) ? Hlo : Hhi;
        const uint32_t* Bb = (pass == 1) ? (const uint32_t*)(smem + OFF_B2LO)
                                         : (const uint32_t*)(smem + OFF_B2HI);
        #pragma unroll
        for (int ks = 0; ks < 3; ks++) {
            int ai = arow2 + tg + 8 * ks;
            uint32_t a0 = Ab[ai],     a1 = Ab[ai + 8 * SH];
            uint32_t a2 = Ab[ai + 4], a3 = Ab[ai + 8 * SH + 4];
            #pragma unroll
            for (int j = 0; j < 11; j++) {
                int bi = (8 * j + g) * SB2 + tg + 8 * ks;
                mma_bf16(acc2[j], a0, a1, a2, a3, Bb[bi], Bb[bi + 4]);
            }
        }
    }

    // ---- epilogue 2: + bias -> global (STG.64) ----
    {
        const int tok0 = 16 * w + g;
        float* ob0 = out + ((size_t)tile * TOK_TILE + tok0) * DATA_DIM;
        float* ob1 = ob0 + 8 * DATA_DIM;
        #pragma unroll
        for (int j = 0; j < 11; j++) {
            int n0 = 8 * j + 2 * tg;
            float b0 = sBhl[n0], b1 = sBhl[n0 + 1];
            float2 v0, v1;
            v0.x = acc2[j][0] + b0; v0.y = acc2[j][1] + b1;
            v1.x = acc2[j][2] + b0; v1.y = acc2[j][3] + b1;
            *(float2*)(ob0 + n0) = v0;
            *(float2*)(ob1 + n0) = v1;
        }
    }
}

extern "C" void kernel_launch(void* const* d_in, const int* in_sizes, int n_in,
                              void* d_out, int out_size)
{
    const int*   w     = (const int*)d_in[0];
    const int*   x     = (const int*)d_in[1];
    const float* y     = (const float*)d_in[2];
    const float* Wxh   = (const float*)d_in[3];
    const float* bxh   = (const float*)d_in[4];
    const float* Wwh   = (const float*)d_in[5];
    const float* bwh   = (const float*)d_in[6];
    const float* Wyh   = (const float*)d_in[7];
    const float* byh   = (const float*)d_in[8];
    const float* Wconv = (const float*)d_in[9];
    const float* bconv = (const float*)d_in[10];
    const float* Whl   = (const float*)d_in[11];
    const float* bhl   = (const float*)d_in[12];
    float* out = (float*)d_out;

    const int tok_total = in_sizes[2] / DATA_DIM;
    const int ntiles = tok_total / TOK_TILE;

    cudaFuncSetAttribute(model8_mma,
                         cudaFuncAttributeMaxDynamicSharedMemorySize, SMEM_TOTAL);

    model8_mma<<<ntiles, THREADS, SMEM_TOTAL>>>(
        w, x, y, Wxh, bxh, Wwh, bwh, Wyh, byh, Wconv, bconv, Whl, bhl, out);
}

// round 12
// speedup vs baseline: 1.0109x; 1.0109x over previous
#include <cuda_runtime.h>
#include <cuda_bf16.h>
#include <cstdint>

#define DATA_DIM 88
#define HID 16
#define ND 48
#define CD 176
#define TOK_TILE 128
#define THREADS 256

// strides in u32 (pair) units; all ≡ 28 (mod 32) => conflict-free fragment loads
#define SA1 92     // A1: 88 data pairs
#define SB1 92     // B1: 88 data pairs
#define SH  28     // H:  24 data pairs
#define SB2 28     // B2: 24 data pairs

// SMEM byte offsets
#define OFF_A1HI 0
#define OFF_A1LO 47104
#define OFF_B1HI 94208
#define OFF_B1LO 111872
#define OFF_HHI  129536
#define OFF_HLO  143872
#define OFF_B2HI 158208
#define OFF_B2LO 168064
#define OFF_WXH  177920
#define OFF_WWH  180992
#define OFF_BSUM 184064
#define OFF_BHL  184256
#define OFF_XI   184608
#define OFF_WI   185120
#define SMEM_TOTAL 185632

__device__ __forceinline__ uint32_t cvt_bf2(float lo, float hi) {
    uint32_t r;
    asm("cvt.rn.bf16x2.f32 %0, %1, %2;" : "=r"(r) : "f"(hi), "f"(lo));
    return r;
}
__device__ __forceinline__ float bfr(float v) {
    return __bfloat162float(__float2bfloat16_rn(v));
}
__device__ __forceinline__ void mma_bf16(float* c,
                                         uint32_t a0, uint32_t a1, uint32_t a2, uint32_t a3,
                                         uint32_t b0, uint32_t b1) {
    asm volatile(
        "mma.sync.aligned.m16n8k16.row.col.f32.bf16.bf16.f32 "
        "{%0,%1,%2,%3}, {%4,%5,%6,%7}, {%8,%9}, {%0,%1,%2,%3};\n"
        : "+f"(c[0]), "+f"(c[1]), "+f"(c[2]), "+f"(c[3])
        : "r"(a0), "r"(a1), "r"(a2), "r"(a3), "r"(b0), "r"(b1));
}

// conv output for tone d (d is a compile-time constant after unroll)
#define CONV(d) fmaxf(fmaf(wc2, ((d) == 87 ? 0.f : yr[(d) + 1]), \
                      fmaf(wc1, yr[d], fmaf(wc0, ((d) == 0 ? 0.f : yr[(d) - 1]), bc))), 0.f)

__global__ void __launch_bounds__(THREADS, 1)
model8_mma(const int* __restrict__ gw, const int* __restrict__ gx,
           const float* __restrict__ gy,
           const float* __restrict__ Wxh, const float* __restrict__ bxh,
           const float* __restrict__ Wwh, const float* __restrict__ bwh,
           const float* __restrict__ Wyh, const float* __restrict__ byh,
           const float* __restrict__ Wconv, const float* __restrict__ bconv,
           const float* __restrict__ Whl, const float* __restrict__ bhl,
           float* __restrict__ out)
{
    extern __shared__ char smem[];
    uint32_t* A1hi = (uint32_t*)(smem + OFF_A1HI);
    uint32_t* A1lo = (uint32_t*)(smem + OFF_A1LO);
    uint32_t* Hhi  = (uint32_t*)(smem + OFF_HHI);
    uint32_t* Hlo  = (uint32_t*)(smem + OFF_HLO);
    float*    sWxh = (float*)(smem + OFF_WXH);
    float*    sWwh = (float*)(smem + OFF_WWH);
    float*    sBsum= (float*)(smem + OFF_BSUM);
    float*    sBhl = (float*)(smem + OFF_BHL);
    int*      sXI  = (int*)(smem + OFF_XI);
    int*      sWI  = (int*)(smem + OFF_WI);

    const int tid  = threadIdx.x;
    const int tile = blockIdx.x;

    // ---- per-thread conv assignment: token = tid/2, channel = tid&1 ----
    const int token = tid >> 1;
    const int ch    = tid & 1;

    // load y row into registers (22 x LDG.128)
    float yr[DATA_DIM];
    {
        const float4* yrow = (const float4*)(gy + ((size_t)tile * TOK_TILE + token) * DATA_DIM);
        #pragma unroll
        for (int q = 0; q < 22; q++) {
            float4 v = yrow[q];
            yr[4*q] = v.x; yr[4*q+1] = v.y; yr[4*q+2] = v.z; yr[4*q+3] = v.w;
        }
    }
    const float wc0 = __ldg(&Wconv[ch * 3 + 0]);
    const float wc1 = __ldg(&Wconv[ch * 3 + 1]);
    const float wc2 = __ldg(&Wconv[ch * 3 + 2]);
    const float bc  = __ldg(&bconv[ch]);

    // ---- stage weights (bf16 hi/lo split), gathers, biases, indices ----
    for (int i = tid; i < ND * CD; i += THREADS) {
        int n = i / CD, k = i % CD;
        float v = Wyh[i];
        float h = bfr(v);
        uint32_t bo = (uint32_t)(n * SA1 + (k >> 1)) * 4u + (uint32_t)(k & 1) * 2u;
        *(__nv_bfloat16*)(smem + OFF_B1HI + bo) = __float2bfloat16_rn(v);
        *(__nv_bfloat16*)(smem + OFF_B1LO + bo) = __float2bfloat16_rn(v - h);
    }
    for (int i = tid; i < DATA_DIM * ND; i += THREADS) {
        int d = i / ND, k = i % ND;
        float v = Whl[i];
        float h = bfr(v);
        uint32_t bo = (uint32_t)(d * SB2 + (k >> 1)) * 4u + (uint32_t)(k & 1) * 2u;
        *(__nv_bfloat16*)(smem + OFF_B2HI + bo) = __float2bfloat16_rn(v);
        *(__nv_bfloat16*)(smem + OFF_B2LO + bo) = __float2bfloat16_rn(v - h);
    }
    for (int i = tid; i < ND * HID; i += THREADS) {
        int n = i / HID, h = i % HID;
        sWxh[h * ND + n] = Wxh[i];
        sWwh[h * ND + n] = Wwh[i];
    }
    for (int i = tid; i < ND; i += THREADS) sBsum[i] = bxh[i] + bwh[i] + byh[i];
    for (int i = tid; i < DATA_DIM; i += THREADS) sBhl[i] = bhl[i];
    for (int i = tid; i < TOK_TILE; i += THREADS) {
        sXI[i] = gx[(size_t)tile * TOK_TILE + i];
        sWI[i] = gw[(size_t)tile * TOK_TILE + i];
    }
    __syncthreads();   // the only block barrier

    // ---- conv + bf16 split -> A1 (each warp writes exactly its own 16 tokens) ----
    {
        uint32_t base = (uint32_t)token * SA1 + (uint32_t)ch * 44u;  // u32 index, 16B-aligned
        uint4* dh = (uint4*)(A1hi + base);
        uint4* dl = (uint4*)(A1lo + base);
        #pragma unroll
        for (int q = 0; q < 11; q++) {
            float c0 = CONV(8*q+0), c1 = CONV(8*q+1), c2 = CONV(8*q+2), c3 = CONV(8*q+3);
            float c4 = CONV(8*q+4), c5 = CONV(8*q+5), c6 = CONV(8*q+6), c7 = CONV(8*q+7);
            uint4 H4, L4;
            H4.x = cvt_bf2(c0, c1); H4.y = cvt_bf2(c2, c3);
            H4.z = cvt_bf2(c4, c5); H4.w = cvt_bf2(c6, c7);
            L4.x = cvt_bf2(c0 - bfr(c0), c1 - bfr(c1));
            L4.y = cvt_bf2(c2 - bfr(c2), c3 - bfr(c3));
            L4.z = cvt_bf2(c4 - bfr(c4), c5 - bfr(c5));
            L4.w = cvt_bf2(c6 - bfr(c6), c7 - bfr(c7));
            dh[q] = H4;
            dl[q] = L4;
        }
    }
    __syncwarp();

    const int w    = tid >> 5;
    const int lane = tid & 31;
    const int g    = lane >> 2;
    const int tg   = lane & 3;

    // ---- GEMM1: [128x176] x [176x48]^T, split-bf16 3 passes ----
    float acc[6][4];
    #pragma unroll
    for (int j = 0; j < 6; j++)
        acc[j][0] = acc[j][1] = acc[j][2] = acc[j][3] = 0.f;

    const int arow1 = (16 * w + g) * SA1;
    #pragma unroll 1
    for (int pass = 0; pass < 3; pass++) {
        const uint32_t* Ab = (pass == 2) ? A1lo : A1hi;
        const uint32_t* Bb = (pass == 1) ? (const uint32_t*)(smem + OFF_B1LO)
                                         : (const uint32_t*)(smem + OFF_B1HI);
        #pragma unroll
        for (int ks = 0; ks < 11; ks++) {
            int ai = arow1 + tg + 8 * ks;
            uint32_t a0 = Ab[ai],            a1 = Ab[ai + 8 * SA1];
            uint32_t a2 = Ab[ai + 4],        a3 = Ab[ai + 8 * SA1 + 4];
            #pragma unroll
            for (int j = 0; j < 6; j++) {
                int bi = (8 * j + g) * SB1 + tg + 8 * ks;
                mma_bf16(acc[j], a0, a1, a2, a3, Bb[bi], Bb[bi + 4]);
            }
        }
    }

    // ---- epilogue 1: + gathers + bias, relu, split -> H (intra-warp) ----
    {
        const int tok0 = 16 * w + g, tok1 = tok0 + 8;
        const int xi0 = sXI[tok0], wi0 = sWI[tok0];
        const int xi1 = sXI[tok1], wi1 = sWI[tok1];
        #pragma unroll
        for (int j = 0; j < 6; j++) {
            int n0 = 8 * j + 2 * tg;
            float bs0 = sBsum[n0],               bs1 = sBsum[n0 + 1];
            float h0 = fmaxf(acc[j][0] + bs0 + sWxh[xi0 * ND + n0]     + sWwh[wi0 * ND + n0],     0.f);
            float h1 = fmaxf(acc[j][1] + bs1 + sWxh[xi0 * ND + n0 + 1] + sWwh[wi0 * ND + n0 + 1], 0.f);
            float h2 = fmaxf(acc[j][2] + bs0 + sWxh[xi1 * ND + n0]     + sWwh[wi1 * ND + n0],     0.f);
            float h3 = fmaxf(acc[j][3] + bs1 + sWxh[xi1 * ND + n0 + 1] + sWwh[wi1 * ND + n0 + 1], 0.f);
            int i0 = tok0 * SH + 4 * j + tg;
            int i1 = tok1 * SH + 4 * j + tg;
            Hhi[i0] = cvt_bf2(h0, h1);
            Hlo[i0] = cvt_bf2(h0 - bfr(h0), h1 - bfr(h1));
            Hhi[i1] = cvt_bf2(h2, h3);
            Hlo[i1] = cvt_bf2(h2 - bfr(h2), h3 - bfr(h3));
        }
    }
    __syncwarp();

    // ---- GEMM2: [128x48] x [48x88]^T, split-bf16 3 passes ----
    float acc2[11][4];
    #pragma unroll
    for (int j = 0; j < 11; j++)
        acc2[j][0] = acc2[j][1] = acc2[j][2] = acc2[j][3] = 0.f;

    const int arow2 = (16 * w + g) * SH;
    #pragma unroll 1
    for (int pass = 0; pass < 3; pass++) {
        const uint32_t* Ab = (pass == 2) ? Hlo : Hhi;
        const uint32_t* Bb = (pass == 1) ? (const uint32_t*)(smem + OFF_B2LO)
                                         : (const uint32_t*)(smem + OFF_B2HI);
        #pragma unroll
        for (int ks = 0; ks < 3; ks++) {
            int ai = arow2 + tg + 8 * ks;
            uint32_t a0 = Ab[ai],     a1 = Ab[ai + 8 * SH];
            uint32_t a2 = Ab[ai + 4], a3 = Ab[ai + 8 * SH + 4];
            #pragma unroll
            for (int j = 0; j < 11; j++) {
                int bi = (8 * j + g) * SB2 + tg + 8 * ks;
                mma_bf16(acc2[j], a0, a1, a2, a3, Bb[bi], Bb[bi + 4]);
            }
        }
    }

    // ---- epilogue 2: + bias -> global (STG.64) ----
    {
        const int tok0 = 16 * w + g;
        float* ob0 = out + ((size_t)tile * TOK_TILE + tok0) * DATA_DIM;
        float* ob1 = ob0 + 8 * DATA_DIM;
        #pragma unroll
        for (int j = 0; j < 11; j++) {
            int n0 = 8 * j + 2 * tg;
            float b0 = sBhl[n0], b1 = sBhl[n0 + 1];
            float2 v0, v1;
            v0.x = acc2[j][0] + b0; v0.y = acc2[j][1] + b1;
            v1.x = acc2[j][2] + b0; v1.y = acc2[j][3] + b1;
            *(float2*)(ob0 + n0) = v0;
            *(float2*)(ob1 + n0) = v1;
        }
    }
}

extern "C" void kernel_launch(void* const* d_in, const int* in_sizes, int n_in,
                              void* d_out, int out_size)
{
    const int*   w     = (const int*)d_in[0];
    const int*   x     = (const int*)d_in[1];
    const float* y     = (const float*)d_in[2];
    const float* Wxh   = (const float*)d_in[3];
    const float* bxh   = (const float*)d_in[4];
    const float* Wwh   = (const float*)d_in[5];
    const float* bwh   = (const float*)d_in[6];
    const float* Wyh   = (const float*)d_in[7];
    const float* byh   = (const float*)d_in[8];
    const float* Wconv = (const float*)d_in[9];
    const float* bconv = (const float*)d_in[10];
    const float* Whl   = (const float*)d_in[11];
    const float* bhl   = (const float*)d_in[12];
    float* out = (float*)d_out;

    const int tok_total = in_sizes[2] / DATA_DIM;
    const int ntiles = tok_total / TOK_TILE;

    cudaFuncSetAttribute(model8_mma,
                         cudaFuncAttributeMaxDynamicSharedMemorySize, SMEM_TOTAL);

    model8_mma<<<ntiles, THREADS, SMEM_TOTAL>>>(
        w, x, y, Wxh, bxh, Wwh, bwh, Wyh, byh, Wconv, bconv, Whl, bhl, out);
}

// round 13
// speedup vs baseline: 1.0146x; 1.0036x over previous
#include <cuda_runtime.h>
#include <cuda_bf16.h>
#include <cstdint>

#define DATA_DIM 88
#define HID 16
#define ND 48
#define CD 176
#define TOK_TILE 128
#define THREADS 256

// strides in u32 (pair) units; all ≡ 28 (mod 32) => conflict-free fragment loads
#define SA1 92     // A1: 88 data pairs
#define SB1 92     // B1: 88 data pairs
#define SH  28     // H:  24 data pairs
#define SB2 28     // B2: 24 data pairs

// SMEM byte offsets
#define OFF_A1HI 0
#define OFF_A1LO 47104
#define OFF_B1HI 94208
#define OFF_B1LO 111872
#define OFF_HHI  129536
#define OFF_HLO  143872
#define OFF_B2HI 158208
#define OFF_B2LO 168064
#define OFF_WXH  177920
#define OFF_WWH  180992
#define OFF_BSUM 184064
#define OFF_BHL  184256
#define OFF_XI   184608
#define OFF_WI   185120
#define SMEM_TOTAL 185632

__device__ __forceinline__ uint32_t cvt_bf2(float lo, float hi) {
    uint32_t r;
    asm("cvt.rn.bf16x2.f32 %0, %1, %2;" : "=r"(r) : "f"(hi), "f"(lo));
    return r;
}
__device__ __forceinline__ float bfr(float v) {
    return __bfloat162float(__float2bfloat16_rn(v));
}
__device__ __forceinline__ void mma_bf16(float* c,
                                         uint32_t a0, uint32_t a1, uint32_t a2, uint32_t a3,
                                         uint32_t b0, uint32_t b1) {
    asm volatile(
        "mma.sync.aligned.m16n8k16.row.col.f32.bf16.bf16.f32 "
        "{%0,%1,%2,%3}, {%4,%5,%6,%7}, {%8,%9}, {%0,%1,%2,%3};\n"
        : "+f"(c[0]), "+f"(c[1]), "+f"(c[2]), "+f"(c[3])
        : "r"(a0), "r"(a1), "r"(a2), "r"(a3), "r"(b0), "r"(b1));
}

// conv output for tone d (d is a compile-time constant after unroll)
#define CONV(d) fmaxf(fmaf(wc2, ((d) == 87 ? 0.f : yr[(d) + 1]), \
                      fmaf(wc1, yr[d], fmaf(wc0, ((d) == 0 ? 0.f : yr[(d) - 1]), bc))), 0.f)

__global__ void __launch_bounds__(THREADS, 1)
model8_mma(const int* __restrict__ gw, const int* __restrict__ gx,
           const float* __restrict__ gy,
           const float* __restrict__ Wxh, const float* __restrict__ bxh,
           const float* __restrict__ Wwh, const float* __restrict__ bwh,
           const float* __restrict__ Wyh, const float* __restrict__ byh,
           const float* __restrict__ Wconv, const float* __restrict__ bconv,
           const float* __restrict__ Whl, const float* __restrict__ bhl,
           float* __restrict__ out)
{
    extern __shared__ char smem[];
    uint32_t* A1hi = (uint32_t*)(smem + OFF_A1HI);
    uint32_t* A1lo = (uint32_t*)(smem + OFF_A1LO);
    uint32_t* Hhi  = (uint32_t*)(smem + OFF_HHI);
    uint32_t* Hlo  = (uint32_t*)(smem + OFF_HLO);
    float*    sWxh = (float*)(smem + OFF_WXH);
    float*    sWwh = (float*)(smem + OFF_WWH);
    float*    sBsum= (float*)(smem + OFF_BSUM);
    float*    sBhl = (float*)(smem + OFF_BHL);
    int*      sXI  = (int*)(smem + OFF_XI);
    int*      sWI  = (int*)(smem + OFF_WI);

    const int tid  = threadIdx.x;
    const int tile = blockIdx.x;

    // ---- per-thread conv assignment: token = tid/2, channel = tid&1 ----
    const int token = tid >> 1;
    const int ch    = tid & 1;

    // load y row into registers (22 x LDG.128)
    float yr[DATA_DIM];
    {
        const float4* yrow = (const float4*)(gy + ((size_t)tile * TOK_TILE + token) * DATA_DIM);
        #pragma unroll
        for (int q = 0; q < 22; q++) {
            float4 v = yrow[q];
            yr[4*q] = v.x; yr[4*q+1] = v.y; yr[4*q+2] = v.z; yr[4*q+3] = v.w;
        }
    }
    const float wc0 = __ldg(&Wconv[ch * 3 + 0]);
    const float wc1 = __ldg(&Wconv[ch * 3 + 1]);
    const float wc2 = __ldg(&Wconv[ch * 3 + 2]);
    const float bc  = __ldg(&bconv[ch]);

    // ---- stage weights (bf16 hi/lo split), gathers, biases, indices ----
    for (int i = tid; i < ND * CD; i += THREADS) {
        int n = i / CD, k = i % CD;
        float v = Wyh[i];
        float h = bfr(v);
        uint32_t bo = (uint32_t)(n * SA1 + (k >> 1)) * 4u + (uint32_t)(k & 1) * 2u;
        *(__nv_bfloat16*)(smem + OFF_B1HI + bo) = __float2bfloat16_rn(v);
        *(__nv_bfloat16*)(smem + OFF_B1LO + bo) = __float2bfloat16_rn(v - h);
    }
    for (int i = tid; i < DATA_DIM * ND; i += THREADS) {
        int d = i / ND, k = i % ND;
        float v = Whl[i];
        float h = bfr(v);
        uint32_t bo = (uint32_t)(d * SB2 + (k >> 1)) * 4u + (uint32_t)(k & 1) * 2u;
        *(__nv_bfloat16*)(smem + OFF_B2HI + bo) = __float2bfloat16_rn(v);
        *(__nv_bfloat16*)(smem + OFF_B2LO + bo) = __float2bfloat16_rn(v - h);
    }
    for (int i = tid; i < ND * HID; i += THREADS) {
        int n = i / HID, h = i % HID;
        sWxh[h * ND + n] = Wxh[i];
        sWwh[h * ND + n] = Wwh[i];
    }
    for (int i = tid; i < ND; i += THREADS) sBsum[i] = bxh[i] + bwh[i] + byh[i];
    for (int i = tid; i < DATA_DIM; i += THREADS) sBhl[i] = bhl[i];
    for (int i = tid; i < TOK_TILE; i += THREADS) {
        sXI[i] = gx[(size_t)tile * TOK_TILE + i];
        sWI[i] = gw[(size_t)tile * TOK_TILE + i];
    }
    __syncthreads();   // the only block barrier

    // ---- conv + bf16 split -> A1 (each warp writes exactly its own 16 tokens) ----
    {
        uint32_t base = (uint32_t)token * SA1 + (uint32_t)ch * 44u;  // u32 index, 16B-aligned
        uint4* dh = (uint4*)(A1hi + base);
        uint4* dl = (uint4*)(A1lo + base);
        #pragma unroll
        for (int q = 0; q < 11; q++) {
            float c0 = CONV(8*q+0), c1 = CONV(8*q+1), c2 = CONV(8*q+2), c3 = CONV(8*q+3);
            float c4 = CONV(8*q+4), c5 = CONV(8*q+5), c6 = CONV(8*q+6), c7 = CONV(8*q+7);
            uint4 H4, L4;
            H4.x = cvt_bf2(c0, c1); H4.y = cvt_bf2(c2, c3);
            H4.z = cvt_bf2(c4, c5); H4.w = cvt_bf2(c6, c7);
            L4.x = cvt_bf2(c0 - bfr(c0), c1 - bfr(c1));
            L4.y = cvt_bf2(c2 - bfr(c2), c3 - bfr(c3));
            L4.z = cvt_bf2(c4 - bfr(c4), c5 - bfr(c5));
            L4.w = cvt_bf2(c6 - bfr(c6), c7 - bfr(c7));
            dh[q] = H4;
            dl[q] = L4;
        }
    }
    __syncwarp();

    const int w    = tid >> 5;
    const int lane = tid & 31;
    const int g    = lane >> 2;
    const int tg   = lane & 3;

    // ---- GEMM1: [128x176] x [176x48]^T, split-bf16 3 passes ----
    float acc[6][4];
    #pragma unroll
    for (int j = 0; j < 6; j++)
        acc[j][0] = acc[j][1] = acc[j][2] = acc[j][3] = 0.f;

    const int arow1 = (16 * w + g) * SA1;
    #pragma unroll 1
    for (int pass = 0; pass < 3; pass++) {
        const uint32_t* Ab = (pass == 2) ? A1lo : A1hi;
        const uint32_t* Bb = (pass == 1) ? (const uint32_t*)(smem + OFF_B1LO)
                                         : (const uint32_t*)(smem + OFF_B1HI);
        #pragma unroll
        for (int ks = 0; ks < 11; ks++) {
            int ai = arow1 + tg + 8 * ks;
            uint32_t a0 = Ab[ai],            a1 = Ab[ai + 8 * SA1];
            uint32_t a2 = Ab[ai + 4],        a3 = Ab[ai + 8 * SA1 + 4];
            #pragma unroll
            for (int j = 0; j < 6; j++) {
                int bi = (8 * j + g) * SB1 + tg + 8 * ks;
                mma_bf16(acc[j], a0, a1, a2, a3, Bb[bi], Bb[bi + 4]);
            }
        }
    }

    // ---- epilogue 1: + gathers + bias, relu, split -> H (intra-warp) ----
    {
        const int tok0 = 16 * w + g, tok1 = tok0 + 8;
        const int xi0 = sXI[tok0], wi0 = sWI[tok0];
        const int xi1 = sXI[tok1], wi1 = sWI[tok1];
        #pragma unroll
        for (int j = 0; j < 6; j++) {
            int n0 = 8 * j + 2 * tg;
            float bs0 = sBsum[n0],               bs1 = sBsum[n0 + 1];
            float h0 = fmaxf(acc[j][0] + bs0 + sWxh[xi0 * ND + n0]     + sWwh[wi0 * ND + n0],     0.f);
            float h1 = fmaxf(acc[j][1] + bs1 + sWxh[xi0 * ND + n0 + 1] + sWwh[wi0 * ND + n0 + 1], 0.f);
            float h2 = fmaxf(acc[j][2] + bs0 + sWxh[xi1 * ND + n0]     + sWwh[wi1 * ND + n0],     0.f);
            float h3 = fmaxf(acc[j][3] + bs1 + sWxh[xi1 * ND + n0 + 1] + sWwh[wi1 * ND + n0 + 1], 0.f);
            int i0 = tok0 * SH + 4 * j + tg;
            int i1 = tok1 * SH + 4 * j + tg;
            Hhi[i0] = cvt_bf2(h0, h1);
            Hlo[i0] = cvt_bf2(h0 - bfr(h0), h1 - bfr(h1));
            Hhi[i1] = cvt_bf2(h2, h3);
            Hlo[i1] = cvt_bf2(h2 - bfr(h2), h3 - bfr(h3));
        }
    }
    __syncwarp();

    // ---- GEMM2: [128x48] x [48x88]^T, split-bf16 3 passes ----
    float acc2[11][4];
    #pragma unroll
    for (int j = 0; j < 11; j++)
        acc2[j][0] = acc2[j][1] = acc2[j][2] = acc2[j][3] = 0.f;

    const int arow2 = (16 * w + g) * SH;
    #pragma unroll 1
    for (int pass = 0; pass < 3; pass++) {
        const uint32_t* Ab = (pass == 2) ? Hlo : Hhi;
        const uint32_t* Bb = (pass == 1) ? (const uint32_t*)(smem + OFF_B2LO)
                                         : (const uint32_t*)(smem + OFF_B2HI);
        #pragma unroll
        for (int ks = 0; ks < 3; ks++) {
            int ai = arow2 + tg + 8 * ks;
            uint32_t a0 = Ab[ai],     a1 = Ab[ai + 8 * SH];
            uint32_t a2 = Ab[ai + 4], a3 = Ab[ai + 8 * SH + 4];
            #pragma unroll
            for (int j = 0; j < 11; j++) {
                int bi = (8 * j + g) * SB2 + tg + 8 * ks;
                mma_bf16(acc2[j], a0, a1, a2, a3, Bb[bi], Bb[bi + 4]);
            }
        }
    }

    // ---- epilogue 2: + bias -> global (STG.64) ----
    {
        const int tok0 = 16 * w + g;
        float* ob0 = out + ((size_t)tile * TOK_TILE + tok0) * DATA_DIM;
        float* ob1 = ob0 + 8 * DATA_DIM;
        #pragma unroll
        for (int j = 0; j < 11; j++) {
            int n0 = 8 * j + 2 * tg;
            float b0 = sBhl[n0], b1 = sBhl[n0 + 1];
            float2 v0, v1;
            v0.x = acc2[j][0] + b0; v0.y = acc2[j][1] + b1;
            v1.x = acc2[j][2] + b0; v1.y = acc2[j][3] + b1;
            *(float2*)(ob0 + n0) = v0;
            *(float2*)(ob1 + n0) = v1;
        }
    }
}

extern "C" void kernel_launch(void* const* d_in, const int* in_sizes, int n_in,
                              void* d_out, int out_size)
{
    const int*   w     = (const int*)d_in[0];
    const int*   x     = (const int*)d_in[1];
    const float* y     = (const float*)d_in[2];
    const float* Wxh   = (const float*)d_in[3];
    const float* bxh   = (const float*)d_in[4];
    const float* Wwh   = (const float*)d_in[5];
    const float* bwh   = (const float*)d_in[6];
    const float* Wyh   = (const float*)d_in[7];
    const float* byh   = (const float*)d_in[8];
    const float* Wconv = (const float*)d_in[9];
    const float* bconv = (const float*)d_in[10];
    const float* Whl   = (const float*)d_in[11];
    const float* bhl   = (const float*)d_in[12];
    float* out = (float*)d_out;

    const int tok_total = in_sizes[2] / DATA_DIM;
    const int ntiles = tok_total / TOK_TILE;

    cudaFuncSetAttribute(model8_mma,
                         cudaFuncAttributeMaxDynamicSharedMemorySize, SMEM_TOTAL);

    model8_mma<<<ntiles, THREADS, SMEM_TOTAL>>>(
        w, x, y, Wxh, bxh, Wwh, bwh, Wyh, byh, Wconv, bconv, Whl, bhl, out);
}